// round 12
// baseline (speedup 1.0000x reference)
#include <cuda_runtime.h>
#include <cuda_bf16.h>
#include <math.h>

// Problem dims (fixed for this dataset instance)
#define B_ 32
#define N_ 1024
#define C_ 64
#define D_ 512
#define K_ 20
#define LOG2PI 1.8378770664093453f
#define LOG2E 1.4426950408889634f
#define LN2F 0.6931471805599453f

// Scratch (allocation-free rule: __device__ globals)
__device__ float d_emission[B_ * N_ * C_];   // log2-domain emission (8MB, L2-resident)
__device__ float d_meansT[D_ * C_];
__device__ float d_invvar[D_];
__device__ float d_m2[C_];
__device__ float d_const;
__device__ float d_P[C_ * C_];               // exp(log_softmax(masked trans, axis=0))
__device__ float d_initlp[C_];               // log2 units
__device__ float d_lentab[K_ * C_];          // [duration-1][c], log2 units

__device__ __forceinline__ float ex2(float x) {
  float r; asm("ex2.approx.f32 %0, %1;" : "=f"(r) : "f"(x)); return r;
}
__device__ __forceinline__ float lg2(float x) {
  float r; asm("lg2.approx.f32 %0, %1;" : "=f"(r) : "f"(x)); return r;
}
__device__ __forceinline__ __nv_bfloat16 shfl_xor_b(__nv_bfloat16 v, int m) {
  unsigned short s = __bfloat16_as_ushort(v);
  unsigned int u = __shfl_xor_sync(0xffffffffu, (unsigned int)s, m);
  return __ushort_as_bfloat16((unsigned short)u);
}

// ---------------------------------------------------------------------------
// Small parameter transforms (single CTA)
// ---------------------------------------------------------------------------
__global__ void __launch_bounds__(256) prep_kernel(
    const float* __restrict__ means, const float* __restrict__ cov,
    const float* __restrict__ tl, const float* __restrict__ il,
    const float* __restrict__ plr) {
  int tid = threadIdx.x;
  __shared__ float red[256];
  __shared__ float sme[64 * 65];
  __shared__ float invs[64];

  float lsum = 0.f;
  for (int d = tid; d < D_; d += 256) {
    float var = cov[d * D_ + d];
    d_invvar[d] = 1.0f / var;
    lsum += logf(var);
  }
  red[tid] = lsum;
  __syncthreads();
  for (int o = 128; o > 0; o >>= 1) {
    if (tid < o) red[tid] += red[tid + o];
    __syncthreads();
  }
  if (tid == 0) d_const = -0.5f * (red[0] + (float)D_ * LOG2PI);

  {
    int w = tid >> 5, ln = tid & 31;
    for (int i = 0; i < 8; i++) {
      int cc = w + 8 * i;
      float s = 0.f;
      for (int j = ln; j < D_; j += 32) {
        float mm = means[cc * D_ + j];
        s += mm * mm * d_invvar[j];
      }
      for (int o = 16; o > 0; o >>= 1) s += __shfl_xor_sync(0xffffffffu, s, o);
      if (ln == 0) d_m2[cc] = s;
    }
  }

  for (int idx = tid; idx < 64 * 64; idx += 256) {
    int i = idx >> 6, j = idx & 63;
    sme[i * 65 + j] = (i == j) ? 0.f : expf(tl[i * 64 + j]);
  }
  __syncthreads();
  if (tid < 64) {
    float s = 0.f;
    for (int i = 0; i < 64; i++) s += sme[i * 65 + tid];
    invs[tid] = 1.0f / s;
  }
  __syncthreads();
  for (int idx = tid; idx < 64 * 64; idx += 256) {
    int i = idx >> 6, j = idx & 63;
    d_P[idx] = sme[i * 65 + j] * invs[j];
  }

  if (tid == 0) {
    float mx = -3e38f;
    for (int cc = 0; cc < 64; cc++) mx = fmaxf(mx, il[cc]);
    float s = 0.f;
    for (int cc = 0; cc < 64; cc++) s += expf(il[cc] - mx);
    float l = mx + logf(s);
    for (int cc = 0; cc < 64; cc++) d_initlp[cc] = (il[cc] - l) * LOG2E;
  }

  for (int idx = tid; idx < K_ * 64; idx += 256) {
    int dd = idx >> 6, cc = idx & 63;
    float lr = plr[cc];
    d_lentab[idx] = LOG2E * ((float)(dd + 1) * lr - expf(lr) - lgammaf((float)(dd + 2)));
  }
}

// ---------------------------------------------------------------------------
// Parallel transpose: meansT[d][c] = means[c][d] / var[d]
// ---------------------------------------------------------------------------
__global__ void __launch_bounds__(256) transpose_kernel(const float* __restrict__ means,
                                                        const float* __restrict__ cov) {
  __shared__ float tile[32][33];
  int d0 = blockIdx.x * 32, c0 = blockIdx.y * 32;
  int tx = threadIdx.x & 31, ty = threadIdx.x >> 5;
#pragma unroll
  for (int k = 0; k < 4; k++) {
    int cc = c0 + ty + 8 * k;
    tile[ty + 8 * k][tx] = means[cc * D_ + d0 + tx];
  }
  __syncthreads();
#pragma unroll
  for (int k = 0; k < 4; k++) {
    int dd = d0 + ty + 8 * k;
    float iv = 1.0f / cov[dd * D_ + dd];
    d_meansT[dd * C_ + c0 + tx] = tile[tx][ty + 8 * k] * iv;
  }
}

// ---------------------------------------------------------------------------
// Emission GEMM (log2-domain output)
// ---------------------------------------------------------------------------
__global__ void __launch_bounds__(256) emission_kernel(const float* __restrict__ feat) {
  __shared__ float fs[128][33];
  __shared__ float4 ms4[32][17];
  __shared__ float ivs[32];

  int tid = threadIdx.x;
  int r0 = blockIdx.x * 128;
  int cg = tid & 15;
  int rg = tid >> 4;

  float acc[8][4];
  float xacc[8];
#pragma unroll
  for (int i = 0; i < 8; i++) {
    xacc[i] = 0.f;
#pragma unroll
    for (int j = 0; j < 4; j++) acc[i][j] = 0.f;
  }

  for (int k0 = 0; k0 < D_; k0 += 32) {
#pragma unroll
    for (int ii = 0; ii < 16; ii++) {
      int idx = tid + 256 * ii;
      int row = idx >> 5, col = idx & 31;
      fs[row][col] = feat[(r0 + row) * D_ + k0 + col];
    }
#pragma unroll
    for (int ii = 0; ii < 2; ii++) {
      int idx = tid + 256 * ii;
      int k = idx >> 4, c4 = idx & 15;
      ms4[k][c4] = ((const float4*)(d_meansT + (k0 + k) * C_))[c4];
    }
    if (tid < 32) ivs[tid] = d_invvar[k0 + tid];
    __syncthreads();

#pragma unroll
    for (int k = 0; k < 32; k++) {
      float4 bv = ms4[k][cg];
      float iv = ivs[k];
#pragma unroll
      for (int i = 0; i < 8; i++) {
        float a = fs[rg * 8 + i][k];
        acc[i][0] = fmaf(a, bv.x, acc[i][0]);
        acc[i][1] = fmaf(a, bv.y, acc[i][1]);
        acc[i][2] = fmaf(a, bv.z, acc[i][2]);
        acc[i][3] = fmaf(a, bv.w, acc[i][3]);
        xacc[i] = fmaf(a * a, iv, xacc[i]);
      }
    }
    __syncthreads();
  }

  float cst = d_const;
  float4 m2v = ((const float4*)d_m2)[cg];
#pragma unroll
  for (int i = 0; i < 8; i++) {
    int row = r0 + rg * 8 + i;
    float base = cst - 0.5f * xacc[i];
    float4 o;
    o.x = LOG2E * (acc[i][0] - 0.5f * m2v.x + base);
    o.y = LOG2E * (acc[i][1] - 0.5f * m2v.y + base);
    o.z = LOG2E * (acc[i][2] - 0.5f * m2v.z + base);
    o.w = LOG2E * (acc[i][3] - 0.5f * m2v.w + base);
    ((float4*)(d_emission + row * C_))[cg] = o;
  }
}

// ---------------------------------------------------------------------------
// Semi-Markov scan v9: 128 threads (4 warps), 2 threads/state (h = tid&1).
// h splits the matvec (16 HFMA2 + 4 LDS each) AND the durations (h0: d1..10,
// h1: d11..20; stride-5 bf16x2 pairs + 2 staged scalars; shift = index
// rotation). All-bf16 chain; ONE shfl (acc-merge) on the critical path; the
// partial merge + cross-half handoff shfls hide pre-bar. One bar/step.
// ---------------------------------------------------------------------------
__global__ void __launch_bounds__(128, 1) scan_kernel(const int* __restrict__ lengths,
                                                      float* __restrict__ out) {
  const int b = blockIdx.x;
  const int tid = threadIdx.x;
  const int c = tid >> 1;   // state 0..63
  const int h = tid & 1;    // duration/matvec half

  __shared__ __align__(16) __nv_bfloat16 e_sm[2][64];
  __shared__ float m_sm[2];
  __shared__ float red_sm[4];

  // transition half-row: j = h*32 + [0..31], packed in bf16x2
  __nv_bfloat162 P2[16];
#pragma unroll
  for (int s = 0; s < 16; s++)
    P2[s] = __floats2bfloat162_rn(d_P[c * 64 + h * 32 + 2 * s],
                                  d_P[c * 64 + h * 32 + 2 * s + 1]);

  // duration weights (this half: base = h*10, durations base+1..base+10)
  // LA = Λ_{base+1}, LB = Λ_{base+6}; pairs L2[k] = (Λ_{base+2+k}, Λ_{base+7+k})
  const int dbase = h * 10;
  const __nv_bfloat16 LA = __float2bfloat16(ex2(d_lentab[(dbase + 0) * 64 + c]));
  const __nv_bfloat16 LB = __float2bfloat16(ex2(d_lentab[(dbase + 5) * 64 + c]));
  __nv_bfloat162 L2[4];
#pragma unroll
  for (int k = 0; k < 4; k++)
    L2[k] = __floats2bfloat162_rn(ex2(d_lentab[(dbase + 1 + k) * 64 + c]),
                                  ex2(d_lentab[(dbase + 6 + k) * 64 + c]));

  // ring pairs: at phase P, pair k = (W_{base+2+k}, W_{base+7+k}) at QP[5+k-P]
  __nv_bfloat162 QP[9];
  const __nv_bfloat16 zb = __float2bfloat16(0.f);
#pragma unroll
  for (int i = 0; i < 9; i++) QP[i] = __halves2bfloat162(zb, zb);
  __nv_bfloat16 sA = h ? zb : __float2bfloat16(ex2(d_initlp[c]));  // W_{base+1}
  __nv_bfloat16 sB = zb;                                           // W_{base+6}
  __nv_bfloat16 acc = __float2bfloat16(ex2(d_initlp[c]));          // beta row val

  const int len_b = lengths[b];
  const float* em = d_emission + b * (N_ * C_);
  float emr_a = em[c];            // row 0 = em_1[c]
  float emr_b = em[64 + c];       // row 1
  float emr_c2 = em[128 + c];     // row 2

  float m = em[0] + d_initlp[0] + d_lentab[0];   // exact alpha_1[0] (log2)
  float m_prev = 0.f;
  float beta0_prev = d_initlp[0];

  __nv_bfloat16 my_e = zb;
  float m_save = 0.f;

#define STEP(P)                                                                  \
  {                                                                              \
    const int t = tb + (P) + 1;                                                  \
    const int BUF = t & 1;                                                       \
    int rpre = (t + 2 < N_) ? (t + 2) : (N_ - 1);                                \
    float emNew = em[rpre * 64 + c];                                             \
    float dm = m - m_prev;                                                       \
    float scf = ex2(emr_a - dm);                                                 \
    __nv_bfloat16 scb = __float2bfloat16(scf);                                   \
    __nv_bfloat162 sc2 = __bfloat162bfloat162(scb);                              \
    /* half partial dot over my 10 durations (h0 defers d1 via acc) */           \
    __nv_bfloat162 hA = __hmul2(QP[5 - (P)], L2[0]);                             \
    __nv_bfloat162 hB = __hmul2(QP[6 - (P)], L2[1]);                             \
    hA = __hfma2(QP[7 - (P)], L2[2], hA);                                        \
    hB = __hfma2(QP[8 - (P)], L2[3], hB);                                        \
    hA = __hadd2(hA, hB);                                                        \
    __nv_bfloat16 pb = __hadd(__low2bfloat16(hA), __high2bfloat16(hA));          \
    pb = __hfma(sB, LB, pb);                                                     \
    __nv_bfloat16 tA = h ? sA : zb;                                              \
    pb = __hfma(tA, LA, pb);                                                     \
    __nv_bfloat16 pmg = __hadd(pb, shfl_xor_b(pb, 1));  /* off-chain merge */    \
    __nv_bfloat16 pesc = __hmul(pmg, scb);                                       \
    __nv_bfloat16 LAsc = __hmul(LA, scb);                                        \
    /* expel oldest pair; age; insert fresh; cross-half handoff */               \
    __nv_bfloat162 expl = QP[8 - (P)];                                           \
    __nv_bfloat16 sBn = __hmul(__low2bfloat16(expl), scb);                       \
    __nv_bfloat16 hoff = __hmul(__high2bfloat16(expl), scb);                     \
    __nv_bfloat16 hin = shfl_xor_b(hoff, 1);   /* h1 receives d10->d11 */        \
    QP[4 - (P)] = __hmul2(__halves2bfloat162(sA, sB), sc2);                      \
    QP[5 - (P)] = __hmul2(QP[5 - (P)], sc2);                                     \
    QP[6 - (P)] = __hmul2(QP[6 - (P)], sc2);                                     \
    QP[7 - (P)] = __hmul2(QP[7 - (P)], sc2);                                     \
    sB = sBn;                                                                    \
    /* e_t: single late HFMA on the acc chain (h0's value is the real one) */    \
    __nv_bfloat16 eb = __hfma(acc, LAsc, pesc);                                  \
    if (h == 0) e_sm[BUF][c] = eb;                                               \
    if (tid == 0) m_sm[BUF] = beta0_prev + emr_a + emr_b;                        \
    __syncthreads();                                                             \
    /* half matvec: 4 broadcast LDS.128 over my 32 j's, 4 HFMA2 chains */        \
    const uint4* Ev = (const uint4*)(&e_sm[BUF][h * 32]);                        \
    uint4 u0 = Ev[0], u1 = Ev[1], u2 = Ev[2], u3 = Ev[3];                        \
    const __nv_bfloat162* e0 = (const __nv_bfloat162*)&u0;                       \
    const __nv_bfloat162* e1 = (const __nv_bfloat162*)&u1;                       \
    const __nv_bfloat162* e2p = (const __nv_bfloat162*)&u2;                      \
    const __nv_bfloat162* e3 = (const __nv_bfloat162*)&u3;                       \
    __nv_bfloat162 a0 = __hmul2(P2[0], e0[0]);                                   \
    __nv_bfloat162 a1 = __hmul2(P2[1], e0[1]);                                   \
    __nv_bfloat162 a2 = __hmul2(P2[2], e0[2]);                                   \
    __nv_bfloat162 a3 = __hmul2(P2[3], e0[3]);                                   \
    a0 = __hfma2(P2[4], e1[0], a0);                                              \
    a1 = __hfma2(P2[5], e1[1], a1);                                              \
    a2 = __hfma2(P2[6], e1[2], a2);                                              \
    a3 = __hfma2(P2[7], e1[3], a3);                                              \
    a0 = __hfma2(P2[8], e2p[0], a0);                                             \
    a1 = __hfma2(P2[9], e2p[1], a1);                                             \
    a2 = __hfma2(P2[10], e2p[2], a2);                                            \
    a3 = __hfma2(P2[11], e2p[3], a3);                                            \
    a0 = __hfma2(P2[12], e3[0], a0);                                             \
    a1 = __hfma2(P2[13], e3[1], a1);                                             \
    a2 = __hfma2(P2[14], e3[2], a2);                                             \
    a3 = __hfma2(P2[15], e3[3], a3);                                             \
    a0 = __hadd2(a0, a1);                                                        \
    a2 = __hadd2(a2, a3);                                                        \
    a0 = __hadd2(a0, a2);                                                        \
    __nv_bfloat16 halfacc = __hadd(__low2bfloat16(a0), __high2bfloat16(a0));     \
    __nv_bfloat16 nacc = __hadd(halfacc, shfl_xor_b(halfacc, 1));                \
    float accf = __bfloat162float(nacc);                                         \
    float m_read = m_sm[BUF];                                                    \
    beta0_prev = m + lg2(fmaxf(accf, 1e-30f));                                   \
    bool hit = (t == len_b);                                                     \
    my_e = hit ? eb : my_e;                                                      \
    m_save = hit ? m : m_save;                                                   \
    acc = nacc;                                                                  \
    sA = h ? hin : nacc;                                                         \
    m_prev = m; m = m_read;                                                      \
    emr_a = emr_b; emr_b = emr_c2; emr_c2 = emNew;                               \
  }

  for (int tb = 0; tb < N_; tb += 4) {
    STEP(0)
    STEP(1)
    STEP(2)
    STEP(3)
    // restore group invariant: pair slots rotate up by 4
#pragma unroll
    for (int i = 8; i >= 5; i--) QP[i] = QP[i - 4];
  }
#undef STEP

  // final logZ = m_save + log2(sum_c e_c(len))   (h1 lanes contribute 0)
  float ef = h ? 0.f : __bfloat162float(my_e);
#pragma unroll
  for (int o = 16; o > 0; o >>= 1) ef += __shfl_xor_sync(0xffffffffu, ef, o);
  if ((tid & 31) == 0) red_sm[tid >> 5] = ef;
  __syncthreads();
  if (tid == 0)
    out[b] = (m_save + lg2(red_sm[0] + red_sm[1] + red_sm[2] + red_sm[3])) * LN2F;
}

// ---------------------------------------------------------------------------
extern "C" void kernel_launch(void* const* d_in, const int* in_sizes, int n_in,
                              void* d_out, int out_size) {
  const float* feat    = (const float*)d_in[0];
  const int*   lengths = (const int*)d_in[1];
  const float* means   = (const float*)d_in[2];
  const float* cov     = (const float*)d_in[3];
  const float* tl      = (const float*)d_in[4];
  const float* il      = (const float*)d_in[5];
  const float* plr     = (const float*)d_in[6];
  float* out = (float*)d_out;

  prep_kernel<<<1, 256>>>(means, cov, tl, il, plr);
  transpose_kernel<<<dim3(16, 2), 256>>>(means, cov);
  emission_kernel<<<(B_ * N_) / 128, 256>>>(feat);
  scan_kernel<<<B_, 128>>>(lengths, out);
}

// round 13
// speedup vs baseline: 1.1787x; 1.1787x over previous
#include <cuda_runtime.h>
#include <cuda_bf16.h>
#include <math.h>

// Problem dims (fixed for this dataset instance)
#define B_ 32
#define N_ 1024
#define NP_ (N_ + 8)   // padded rows per batch (prefetch overrun safe)
#define C_ 64
#define D_ 512
#define K_ 20
#define LOG2PI 1.8378770664093453f
#define LOG2E 1.4426950408889634f
#define LN2F 0.6931471805599453f

// Scratch (allocation-free rule: __device__ globals)
__device__ float d_emission[B_ * NP_ * C_];  // log2-domain emission, padded
__device__ float d_meansT[D_ * C_];
__device__ float d_invvar[D_];
__device__ float d_m2[C_];
__device__ float d_const;
__device__ float d_P[C_ * C_];               // exp(log_softmax(masked trans, axis=0))
__device__ float d_initlp[C_];               // log2 units
__device__ float d_lentab[K_ * C_];          // [duration-1][c], log2 units

__device__ __forceinline__ float ex2(float x) {
  float r; asm("ex2.approx.f32 %0, %1;" : "=f"(r) : "f"(x)); return r;
}
__device__ __forceinline__ float lg2(float x) {
  float r; asm("lg2.approx.f32 %0, %1;" : "=f"(r) : "f"(x)); return r;
}

// ---------------------------------------------------------------------------
// Small parameter transforms (single CTA)
// ---------------------------------------------------------------------------
__global__ void __launch_bounds__(256) prep_kernel(
    const float* __restrict__ means, const float* __restrict__ cov,
    const float* __restrict__ tl, const float* __restrict__ il,
    const float* __restrict__ plr) {
  int tid = threadIdx.x;
  __shared__ float red[256];
  __shared__ float sme[64 * 65];
  __shared__ float invs[64];

  float lsum = 0.f;
  for (int d = tid; d < D_; d += 256) {
    float var = cov[d * D_ + d];
    d_invvar[d] = 1.0f / var;
    lsum += logf(var);
  }
  red[tid] = lsum;
  __syncthreads();
  for (int o = 128; o > 0; o >>= 1) {
    if (tid < o) red[tid] += red[tid + o];
    __syncthreads();
  }
  if (tid == 0) d_const = -0.5f * (red[0] + (float)D_ * LOG2PI);

  {
    int w = tid >> 5, ln = tid & 31;
    for (int i = 0; i < 8; i++) {
      int cc = w + 8 * i;
      float s = 0.f;
      for (int j = ln; j < D_; j += 32) {
        float mm = means[cc * D_ + j];
        s += mm * mm * d_invvar[j];
      }
      for (int o = 16; o > 0; o >>= 1) s += __shfl_xor_sync(0xffffffffu, s, o);
      if (ln == 0) d_m2[cc] = s;
    }
  }

  for (int idx = tid; idx < 64 * 64; idx += 256) {
    int i = idx >> 6, j = idx & 63;
    sme[i * 65 + j] = (i == j) ? 0.f : expf(tl[i * 64 + j]);
  }
  __syncthreads();
  if (tid < 64) {
    float s = 0.f;
    for (int i = 0; i < 64; i++) s += sme[i * 65 + tid];
    invs[tid] = 1.0f / s;
  }
  __syncthreads();
  for (int idx = tid; idx < 64 * 64; idx += 256) {
    int i = idx >> 6, j = idx & 63;
    d_P[idx] = sme[i * 65 + j] * invs[j];
  }

  if (tid == 0) {
    float mx = -3e38f;
    for (int cc = 0; cc < 64; cc++) mx = fmaxf(mx, il[cc]);
    float s = 0.f;
    for (int cc = 0; cc < 64; cc++) s += expf(il[cc] - mx);
    float l = mx + logf(s);
    for (int cc = 0; cc < 64; cc++) d_initlp[cc] = (il[cc] - l) * LOG2E;
  }

  for (int idx = tid; idx < K_ * 64; idx += 256) {
    int dd = idx >> 6, cc = idx & 63;
    float lr = plr[cc];
    d_lentab[idx] = LOG2E * ((float)(dd + 1) * lr - expf(lr) - lgammaf((float)(dd + 2)));
  }
}

// ---------------------------------------------------------------------------
// Parallel transpose: meansT[d][c] = means[c][d] / var[d]
// ---------------------------------------------------------------------------
__global__ void __launch_bounds__(256) transpose_kernel(const float* __restrict__ means,
                                                        const float* __restrict__ cov) {
  __shared__ float tile[32][33];
  int d0 = blockIdx.x * 32, c0 = blockIdx.y * 32;
  int tx = threadIdx.x & 31, ty = threadIdx.x >> 5;
#pragma unroll
  for (int k = 0; k < 4; k++) {
    int cc = c0 + ty + 8 * k;
    tile[ty + 8 * k][tx] = means[cc * D_ + d0 + tx];
  }
  __syncthreads();
#pragma unroll
  for (int k = 0; k < 4; k++) {
    int dd = d0 + ty + 8 * k;
    float iv = 1.0f / cov[dd * D_ + dd];
    d_meansT[dd * C_ + c0 + tx] = tile[tx][ty + 8 * k] * iv;
  }
}

// ---------------------------------------------------------------------------
// Emission GEMM (log2-domain output, padded batch stride)
// ---------------------------------------------------------------------------
__global__ void __launch_bounds__(256) emission_kernel(const float* __restrict__ feat) {
  __shared__ float fs[128][33];
  __shared__ float4 ms4[32][17];
  __shared__ float ivs[32];

  int tid = threadIdx.x;
  int r0 = blockIdx.x * 128;
  int cg = tid & 15;
  int rg = tid >> 4;

  // 128-row blocks never cross a batch boundary (1024 % 128 == 0)
  const int bb = r0 >> 10;
  float* outb = d_emission + bb * (NP_ * C_) + (r0 - bb * N_) * C_;

  float acc[8][4];
  float xacc[8];
#pragma unroll
  for (int i = 0; i < 8; i++) {
    xacc[i] = 0.f;
#pragma unroll
    for (int j = 0; j < 4; j++) acc[i][j] = 0.f;
  }

  for (int k0 = 0; k0 < D_; k0 += 32) {
#pragma unroll
    for (int ii = 0; ii < 16; ii++) {
      int idx = tid + 256 * ii;
      int row = idx >> 5, col = idx & 31;
      fs[row][col] = feat[(r0 + row) * D_ + k0 + col];
    }
#pragma unroll
    for (int ii = 0; ii < 2; ii++) {
      int idx = tid + 256 * ii;
      int k = idx >> 4, c4 = idx & 15;
      ms4[k][c4] = ((const float4*)(d_meansT + (k0 + k) * C_))[c4];
    }
    if (tid < 32) ivs[tid] = d_invvar[k0 + tid];
    __syncthreads();

#pragma unroll
    for (int k = 0; k < 32; k++) {
      float4 bv = ms4[k][cg];
      float iv = ivs[k];
#pragma unroll
      for (int i = 0; i < 8; i++) {
        float a = fs[rg * 8 + i][k];
        acc[i][0] = fmaf(a, bv.x, acc[i][0]);
        acc[i][1] = fmaf(a, bv.y, acc[i][1]);
        acc[i][2] = fmaf(a, bv.z, acc[i][2]);
        acc[i][3] = fmaf(a, bv.w, acc[i][3]);
        xacc[i] = fmaf(a * a, iv, xacc[i]);
      }
    }
    __syncthreads();
  }

  float cst = d_const;
  float4 m2v = ((const float4*)d_m2)[cg];
#pragma unroll
  for (int i = 0; i < 8; i++) {
    float base = cst - 0.5f * xacc[i];
    float4 o;
    o.x = LOG2E * (acc[i][0] - 0.5f * m2v.x + base);
    o.y = LOG2E * (acc[i][1] - 0.5f * m2v.y + base);
    o.z = LOG2E * (acc[i][2] - 0.5f * m2v.z + base);
    o.w = LOG2E * (acc[i][3] - 0.5f * m2v.w + base);
    ((float4*)(outb + (rg * 8 + i) * C_))[cg] = o;
  }
}

// ---------------------------------------------------------------------------
// Semi-Markov scan v10: v8 structure (2 warps, 1 state/lane, all-bf16 chain)
// + padded unconditional prefetch, x8 unroll, dead-rescale removed,
// fast path for lengths == N (no per-step capture ops).
// ---------------------------------------------------------------------------
__global__ void __launch_bounds__(64, 1) scan_kernel(const int* __restrict__ lengths,
                                                     float* __restrict__ out) {
  const int b = blockIdx.x;
  const int c = threadIdx.x;   // state 0..63

  __shared__ __align__(16) __nv_bfloat16 e_sm[2][64];
  __shared__ float m_sm[2];
  __shared__ float red_sm[2];

  // transition row, packed along j
  __nv_bfloat162 P2[32];
#pragma unroll
  for (int s = 0; s < 32; s++)
    P2[s] = __floats2bfloat162_rn(d_P[c * 64 + 2 * s], d_P[c * 64 + 2 * s + 1]);

  // duration weights Λ_d = 2^len_d : scalars d=1,11; pairs (Λ_{2+k}, Λ_{12+k}) k=0..8
  const __nv_bfloat16 L1b = __float2bfloat16(ex2(d_lentab[0 * 64 + c]));
  const __nv_bfloat16 L11b = __float2bfloat16(ex2(d_lentab[10 * 64 + c]));
  __nv_bfloat162 L2[9];
#pragma unroll
  for (int k = 0; k < 9; k++)
    L2[k] = __floats2bfloat162_rn(ex2(d_lentab[(k + 1) * 64 + c]),
                                  ex2(d_lentab[(k + 11) * 64 + c]));

  // ring: at phase P (0..7), pair j (j=0..8 == durations (2+j,12+j)) at Q[j+9-P];
  // fresh pair written at Q[8-P]; expelled = Q[17-P].
  __nv_bfloat162 Q[18];
  const __nv_bfloat16 zb = __float2bfloat16(0.f);
#pragma unroll
  for (int i = 0; i < 18; i++) Q[i] = __halves2bfloat162(zb, zb);
  __nv_bfloat16 accb = __float2bfloat16(ex2(d_initlp[c]));   // W1 entering step 1
  __nv_bfloat16 W11b = zb;

  const int len_b = lengths[b];
  const float* em = d_emission + b * (NP_ * C_);
  float emr_a = em[c];            // row 0 = em_1[c]
  float emr_b = em[64 + c];       // row 1
  float emr_c2 = em[128 + c];     // row 2

  float m = em[0] + d_initlp[0] + d_lentab[0];   // exact alpha_1[0] (log2)
  float m_prev = 0.f;
  float beta0_prev = d_initlp[0];

  __nv_bfloat16 my_e = zb;
  float m_save = 0.f;

#define STEP(P, CHK)                                                             \
  {                                                                              \
    const int t = tb + (P) + 1;                                                  \
    const int BUF = t & 1;                                                       \
    float emNew = em[(t + 2) * 64 + c];   /* padded buffer: always safe */       \
    float dm = m - m_prev;                                                       \
    float scf = ex2(emr_a - dm);                                                 \
    __nv_bfloat16 scb = __float2bfloat16(scf);                                   \
    __nv_bfloat162 sc2 = __bfloat162bfloat162(scb);                              \
    /* old-only partial dot (d=2..10,12..20 pairs; d=11 scalar) */               \
    __nv_bfloat162 ha = __hmul2(Q[9 - (P)], L2[0]);                              \
    __nv_bfloat162 hb = __hmul2(Q[10 - (P)], L2[1]);                             \
    ha = __hfma2(Q[11 - (P)], L2[2], ha);                                        \
    hb = __hfma2(Q[12 - (P)], L2[3], hb);                                        \
    ha = __hfma2(Q[13 - (P)], L2[4], ha);                                        \
    hb = __hfma2(Q[14 - (P)], L2[5], hb);                                        \
    ha = __hfma2(Q[15 - (P)], L2[6], ha);                                        \
    hb = __hfma2(Q[16 - (P)], L2[7], hb);                                        \
    ha = __hfma2(Q[17 - (P)], L2[8], ha);                                        \
    ha = __hadd2(ha, hb);                                                        \
    __nv_bfloat16 pb = __hadd(__low2bfloat16(ha), __high2bfloat16(ha));          \
    pb = __hfma(W11b, L11b, pb);                                                 \
    __nv_bfloat16 peb = __hmul(pb, scb);                                         \
    __nv_bfloat16 Lsc = __hmul(L1b, scb);                                        \
    /* aging d10->d11 (low half of expelled pair), fresh pair (d2,d12) */        \
    __nv_bfloat16 W11n = __hmul(__low2bfloat16(Q[17 - (P)]), scb);               \
    Q[8 - (P)] = __hmul2(__halves2bfloat162(accb, W11b), sc2);                   \
    _Pragma("unroll")                                                            \
    for (int i = 9 - (P); i <= 16 - (P); i++)   /* survivors only (8 pairs) */   \
      Q[i] = __hmul2(Q[i], sc2);                                                 \
    /* e_t = acc*Λ1*sc + pe : pure bf16, no cvt on chain */                      \
    __nv_bfloat16 eb = __hfma(accb, Lsc, peb);                                   \
    e_sm[BUF][c] = eb;                                                           \
    if (c == 0) m_sm[BUF] = beta0_prev + emr_a + emr_b;                          \
    __syncthreads();                                                             \
    /* matvec: 8 broadcast LDS.128, 8 HFMA2 chains */                            \
    const uint4* Ev = (const uint4*)&e_sm[BUF][0];                               \
    uint4 u0 = Ev[0], u1 = Ev[1], u2 = Ev[2], u3 = Ev[3];                        \
    const __nv_bfloat162* e0 = (const __nv_bfloat162*)&u0;                       \
    const __nv_bfloat162* e1 = (const __nv_bfloat162*)&u1;                       \
    const __nv_bfloat162* e2p = (const __nv_bfloat162*)&u2;                      \
    const __nv_bfloat162* e3 = (const __nv_bfloat162*)&u3;                       \
    __nv_bfloat162 a0 = __hmul2(P2[0], e0[0]);                                   \
    __nv_bfloat162 a1 = __hmul2(P2[1], e0[1]);                                   \
    __nv_bfloat162 a2 = __hmul2(P2[2], e0[2]);                                   \
    __nv_bfloat162 a3 = __hmul2(P2[3], e0[3]);                                   \
    __nv_bfloat162 a4 = __hmul2(P2[4], e1[0]);                                   \
    __nv_bfloat162 a5 = __hmul2(P2[5], e1[1]);                                   \
    __nv_bfloat162 a6 = __hmul2(P2[6], e1[2]);                                   \
    __nv_bfloat162 a7 = __hmul2(P2[7], e1[3]);                                   \
    a0 = __hfma2(P2[8], e2p[0], a0);                                             \
    a1 = __hfma2(P2[9], e2p[1], a1);                                             \
    a2 = __hfma2(P2[10], e2p[2], a2);                                            \
    a3 = __hfma2(P2[11], e2p[3], a3);                                            \
    a4 = __hfma2(P2[12], e3[0], a4);                                             \
    a5 = __hfma2(P2[13], e3[1], a5);                                             \
    a6 = __hfma2(P2[14], e3[2], a6);                                             \
    a7 = __hfma2(P2[15], e3[3], a7);                                             \
    uint4 v0 = Ev[4], v1 = Ev[5], v2 = Ev[6], v3 = Ev[7];                        \
    const __nv_bfloat162* f0p = (const __nv_bfloat162*)&v0;                      \
    const __nv_bfloat162* f1p = (const __nv_bfloat162*)&v1;                      \
    const __nv_bfloat162* f2p = (const __nv_bfloat162*)&v2;                      \
    const __nv_bfloat162* f3p = (const __nv_bfloat162*)&v3;                      \
    a0 = __hfma2(P2[16], f0p[0], a0);                                            \
    a1 = __hfma2(P2[17], f0p[1], a1);                                            \
    a2 = __hfma2(P2[18], f0p[2], a2);                                            \
    a3 = __hfma2(P2[19], f0p[3], a3);                                            \
    a4 = __hfma2(P2[20], f1p[0], a4);                                            \
    a5 = __hfma2(P2[21], f1p[1], a5);                                            \
    a6 = __hfma2(P2[22], f1p[2], a6);                                            \
    a7 = __hfma2(P2[23], f1p[3], a7);                                            \
    a0 = __hfma2(P2[24], f2p[0], a0);                                            \
    a1 = __hfma2(P2[25], f2p[1], a1);                                            \
    a2 = __hfma2(P2[26], f2p[2], a2);                                            \
    a3 = __hfma2(P2[27], f2p[3], a3);                                            \
    a4 = __hfma2(P2[28], f3p[0], a4);                                            \
    a5 = __hfma2(P2[29], f3p[1], a5);                                            \
    a6 = __hfma2(P2[30], f3p[2], a6);                                            \
    a7 = __hfma2(P2[31], f3p[3], a7);                                            \
    a0 = __hadd2(a0, a1); a2 = __hadd2(a2, a3);                                  \
    a4 = __hadd2(a4, a5); a6 = __hadd2(a6, a7);                                  \
    a0 = __hadd2(a0, a2); a4 = __hadd2(a4, a6);                                  \
    a0 = __hadd2(a0, a4);                                                        \
    __nv_bfloat16 nacc = __hadd(__low2bfloat16(a0), __high2bfloat16(a0));        \
    float accf = __bfloat162float(nacc);                                         \
    float m_read = m_sm[BUF];                                                    \
    beta0_prev = m + lg2(fmaxf(accf, 1e-30f));                                   \
    if (CHK) {                                                                   \
      bool hit = (t == len_b);                                                   \
      my_e = hit ? eb : my_e;                                                    \
      m_save = hit ? m : m_save;                                                 \
    }                                                                            \
    W11b = W11n; accb = nacc;                                                    \
    m_prev = m; m = m_read;                                                      \
    emr_a = emr_b; emr_b = emr_c2; emr_c2 = emNew;                               \
  }

#define ROT8()                                                                   \
  {                                                                              \
    _Pragma("unroll")                                                            \
    for (int i = 17; i >= 9; i--) Q[i] = Q[i - 8];                               \
  }

  float ef;
  if (len_b == N_) {
    // fast path: no per-step capture; t=N state recovered after the loop
    for (int tb = 0; tb < N_; tb += 8) {
      STEP(0, false) STEP(1, false) STEP(2, false) STEP(3, false)
      STEP(4, false) STEP(5, false) STEP(6, false) STEP(7, false)
      ROT8()
    }
    m_save = m_prev;                        // m at t = N
    ef = __bfloat162float(e_sm[0][c]);      // e at t = N  (BUF = N&1 = 0)
  } else {
    for (int tb = 0; tb < N_; tb += 8) {
      STEP(0, true) STEP(1, true) STEP(2, true) STEP(3, true)
      STEP(4, true) STEP(5, true) STEP(6, true) STEP(7, true)
      ROT8()
    }
    ef = __bfloat162float(my_e);
  }
#undef STEP
#undef ROT8

  // final logZ = m_save + log2(sum_c e_c(len))  (then to nat-log)
#pragma unroll
  for (int o = 16; o > 0; o >>= 1) ef += __shfl_xor_sync(0xffffffffu, ef, o);
  if ((c & 31) == 0) red_sm[c >> 5] = ef;
  __syncthreads();
  if (c == 0) out[b] = (m_save + lg2(red_sm[0] + red_sm[1])) * LN2F;
}

// ---------------------------------------------------------------------------
extern "C" void kernel_launch(void* const* d_in, const int* in_sizes, int n_in,
                              void* d_out, int out_size) {
  const float* feat    = (const float*)d_in[0];
  const int*   lengths = (const int*)d_in[1];
  const float* means   = (const float*)d_in[2];
  const float* cov     = (const float*)d_in[3];
  const float* tl      = (const float*)d_in[4];
  const float* il      = (const float*)d_in[5];
  const float* plr     = (const float*)d_in[6];
  float* out = (float*)d_out;

  prep_kernel<<<1, 256>>>(means, cov, tl, il, plr);
  transpose_kernel<<<dim3(16, 2), 256>>>(means, cov);
  emission_kernel<<<(B_ * N_) / 128, 256>>>(feat);
  scan_kernel<<<B_, 64>>>(lengths, out);
}